// round 4
// baseline (speedup 1.0000x reference)
#include <cuda_runtime.h>
#include <math.h>

#define HH   1024
#define LL   8192
#define BB   4
#define KDIM 64
#define KTOT 512

// scratch: assembled normalized filter + post-gelu activations
__device__ float g_filt[HH * KTOT];
__device__ float g_v[(size_t)BB * HH * LL];

// ---------------------------------------------------------------------------
// Kernel 1: assemble multi-scale filter, normalize. one block per head.
// ---------------------------------------------------------------------------
__global__ void build_filter_kernel(const float* __restrict__ k0,
                                    const float* __restrict__ k1,
                                    const float* __restrict__ k2,
                                    const float* __restrict__ k3) {
    int h   = blockIdx.x;
    int tid = threadIdx.x;             // 128 threads
    const float* ks0 = k0 + h * KDIM;
    const float* ks1 = k1 + h * KDIM;
    const float* ks2 = k2 + h * KDIM;
    const float* ks3 = k3 + h * KDIM;

    __shared__ float red[128];
    float vals[4];
    float ss = 0.0f;

    #pragma unroll
    for (int r = 0; r < 4; r++) {
        int t = tid + r * 128;          // tap index 0..511
        float acc = 0.0f;
        #pragma unroll
        for (int i = 0; i < 4; i++) {
            int Li = KDIM << i;          // 64,128,256,512
            if (t < Li) {
                float coord = (t + 0.5f) / (float)(1 << i) - 0.5f;
                coord = fminf(fmaxf(coord, 0.0f), (float)(KDIM - 1));
                int   lo = (int)floorf(coord);
                int   hi = min(lo + 1, KDIM - 1);
                float w  = coord - (float)lo;
                const float* kp = (i == 0) ? ks0 : (i == 1) ? ks1 : (i == 2) ? ks2 : ks3;
                float v = kp[lo] * (1.0f - w) + kp[hi] * w;
                acc += v * (float)(1 << (3 - i));   // scale 8,4,2,1
            }
        }
        vals[r] = acc;
        ss += acc * acc;
    }

    red[tid] = ss;
    __syncthreads();
    for (int s = 64; s > 0; s >>= 1) {
        if (tid < s) red[tid] += red[tid + s];
        __syncthreads();
    }
    float inv = 1.0f / sqrtf(red[0]);

    #pragma unroll
    for (int r = 0; r < 4; r++) {
        int t = tid + r * 128;
        g_filt[h * KTOT + t] = vals[r] * inv;
    }
}

// ---------------------------------------------------------------------------
// Kernel 2: causal 512-tap FIR + D*u skip + exact gelu -> g_v
// 256 threads, 8 contiguous outputs/thread (tile 2048), sliding register
// window over u: per 4-tap group 2x LDS.128 + 32 FFMA  -> FMA-bound.
// ---------------------------------------------------------------------------
#define LT2  2048
#define TH2  256

__global__ __launch_bounds__(TH2) void fir_gelu_kernel(const float* __restrict__ u,
                                                       const float* __restrict__ D) {
    __shared__ float us[KTOT + LT2];    // 2560 floats
    __shared__ float ksm[KTOT];         // 512 floats

    int l0  = blockIdx.x * LT2;
    int h   = blockIdx.y;
    int b   = blockIdx.z;
    int tid = threadIdx.x;

    const float* up = u + ((size_t)(b * HH + h)) * LL;

    // halo+tile load: 2560 floats = 640 float4
    for (int f = tid; f < (KTOT + LT2) / 4; f += TH2) {
        int gi = l0 - KTOT + f * 4;
        float4 v;
        if (gi >= 0) {
            v = *reinterpret_cast<const float4*>(up + gi);
        } else {
            v.x = 0.f; v.y = 0.f; v.z = 0.f; v.w = 0.f;
        }
        *reinterpret_cast<float4*>(&us[f * 4]) = v;
    }
    // filter: 512 floats = 128 float4
    if (tid < KTOT / 4) {
        *reinterpret_cast<float4*>(&ksm[tid * 4]) =
            *reinterpret_cast<const float4*>(&g_filt[h * KTOT + tid * 4]);
    }
    __syncthreads();

    const int bw = KTOT + tid * 8;      // us-index of this thread's output r=0

    float acc[8];
    #pragma unroll
    for (int r = 0; r < 8; r++) acc[r] = 0.0f;

    // register window w[idx] = us[winlow + idx], winlow = bw - 4g - 4
    float w[12];
    {
        float4 a = *reinterpret_cast<const float4*>(&us[bw - 4]);
        float4 c = *reinterpret_cast<const float4*>(&us[bw]);
        float4 e = *reinterpret_cast<const float4*>(&us[bw + 4]);
        w[0] = a.x; w[1] = a.y; w[2]  = a.z; w[3]  = a.w;
        w[4] = c.x; w[5] = c.y; w[6]  = c.z; w[7]  = c.w;
        w[8] = e.x; w[9] = e.y; w[10] = e.z; w[11] = e.w;
    }

    #pragma unroll 4
    for (int g = 0; g < KTOT / 4; g++) {
        if (g > 0) {
            // slide window down by 4: w_new[idx+4] = w_old[idx]
            #pragma unroll
            for (int idx = 11; idx >= 4; idx--) w[idx] = w[idx - 4];
            float4 nv = *reinterpret_cast<const float4*>(&us[bw - 4 * g - 4]);
            w[0] = nv.x; w[1] = nv.y; w[2] = nv.z; w[3] = nv.w;
        }
        float4 kv = *reinterpret_cast<const float4*>(&ksm[4 * g]);
        // t = 4g + j ; u index = bw + r - t -> window offset r - j + 4
        #pragma unroll
        for (int j = 0; j < 4; j++) {
            float kj = (j == 0) ? kv.x : (j == 1) ? kv.y : (j == 2) ? kv.z : kv.w;
            #pragma unroll
            for (int r = 0; r < 8; r++)
                acc[r] += kj * w[r - j + 4];
        }
    }

    float d = D[h];
    const float iS2 = 0.70710678118654752440f;
    float out8[8];
    #pragma unroll
    for (int r = 0; r < 8; r++) {
        float x = acc[r] + d * us[bw + r];
        out8[r] = 0.5f * x * (1.0f + erff(x * iS2));   // exact gelu
    }

    float* vp = g_v + ((size_t)(b * HH + h)) * LL + l0 + tid * 8;
    *reinterpret_cast<float4*>(vp)     = make_float4(out8[0], out8[1], out8[2], out8[3]);
    *reinterpret_cast<float4*>(vp + 4) = make_float4(out8[4], out8[5], out8[6], out8[7]);
}

// ---------------------------------------------------------------------------
// Kernel 3: out[b,o,l] = sum_h W[o,h] * v[b,h,l] + bias[o]
// 128x128 tile, BK=16, 256 threads, 8x8 micro-tile per thread
// ---------------------------------------------------------------------------
#define BM 128
#define BN 128
#define BK 16

__global__ __launch_bounds__(256) void gemm_out_kernel(const float* __restrict__ W,
                                                       const float* __restrict__ bias,
                                                       float* __restrict__ out) {
    __shared__ float Ws[BK][BM + 4];    // pad 4 -> stride 132 floats
    __shared__ float Vs[BK][BN];

    int l0  = blockIdx.x * BN;
    int m0  = blockIdx.y * BM;
    int b   = blockIdx.z;
    int tid = threadIdx.x;
    int tx  = tid & 15;                 // 0..15 -> l
    int ty  = tid >> 4;                 // 0..15 -> o

    float acc[8][8];
    #pragma unroll
    for (int i = 0; i < 8; i++)
        #pragma unroll
        for (int j = 0; j < 8; j++) acc[i][j] = 0.0f;

    const float* vbase = g_v + ((size_t)b * HH) * LL + l0;

    for (int kb = 0; kb < HH; kb += BK) {
        // load W tile: 2048 elems; lanes cover contiguous kk runs (coalesced)
        #pragma unroll
        for (int i = 0; i < 8; i++) {
            int idx = tid + i * 256;
            int kk  = idx & (BK - 1);
            int mm  = idx >> 4;
            Ws[kk][mm] = W[(size_t)(m0 + mm) * HH + kb + kk];
        }
        // load V tile: 2048 elems = 512 float4, contiguous 128 floats per k-row
        #pragma unroll
        for (int i = 0; i < 2; i++) {
            int f   = tid + i * 256;     // float4 index 0..511
            int nn4 = f & 31;            // 32 float4 per row
            int kk  = f >> 5;
            float4 v = *reinterpret_cast<const float4*>(
                vbase + (size_t)(kb + kk) * LL + nn4 * 4);
            *reinterpret_cast<float4*>(&Vs[kk][nn4 * 4]) = v;
        }
        __syncthreads();

        #pragma unroll
        for (int kk = 0; kk < BK; kk++) {
            float af[8], bf[8];
            #pragma unroll
            for (int i = 0; i < 8; i++) af[i] = Ws[kk][ty * 8 + i];
            #pragma unroll
            for (int j = 0; j < 8; j++) bf[j] = Vs[kk][tx * 8 + j];
            #pragma unroll
            for (int i = 0; i < 8; i++)
                #pragma unroll
                for (int j = 0; j < 8; j++)
                    acc[i][j] += af[i] * bf[j];
        }
        __syncthreads();
    }

    #pragma unroll
    for (int i = 0; i < 8; i++) {
        int o   = m0 + ty * 8 + i;
        float bb = bias[o];
        float* op = out + ((size_t)b * HH + o) * LL + l0 + tx * 8;
        #pragma unroll
        for (int j = 0; j < 8; j++)
            op[j] = acc[i][j] + bb;
    }
}

// ---------------------------------------------------------------------------
extern "C" void kernel_launch(void* const* d_in, const int* in_sizes, int n_in,
                              void* d_out, int out_size) {
    const float* u  = (const float*)d_in[0];
    const float* k0 = (const float*)d_in[1];
    const float* k1 = (const float*)d_in[2];
    const float* k2 = (const float*)d_in[3];
    const float* k3 = (const float*)d_in[4];
    const float* D  = (const float*)d_in[5];
    const float* W  = (const float*)d_in[6];
    const float* b  = (const float*)d_in[7];
    float* out = (float*)d_out;

    build_filter_kernel<<<HH, 128>>>(k0, k1, k2, k3);

    dim3 g2(LL / LT2, HH, BB);
    fir_gelu_kernel<<<g2, TH2>>>(u, D);

    dim3 g3(LL / BN, HH / BM, BB);
    gemm_out_kernel<<<g3, 256>>>(W, b, out);
}

// round 6
// speedup vs baseline: 3.3217x; 3.3217x over previous
#include <cuda_runtime.h>
#include <cuda_bf16.h>
#include <math.h>
#include <stdint.h>

#define HH   1024
#define LL   8192
#define BB   4
#define KDIM 64
#define KTOT 512

// tcgen05 only exists in arch-specific (sm_103a/sm_100a) compilation passes.
#if defined(__CUDA_ARCH_FEAT_SM103_ALL) || defined(__CUDA_ARCH_FEAT_SM100_ALL)
#define HAS_TC 1
#else
#define HAS_TC 0
#endif

// scratch
__device__ float g_filt[HH * KTOT];
__device__ float g_v[(size_t)BB * HH * LL];
__device__ __align__(256) __nv_bfloat16 g_vt[(size_t)BB * LL * 2048]; // [b][l][hi(1024)|lo(1024)]
__device__ __align__(256) __nv_bfloat16 g_ws[(size_t)HH * 2048];      // [o][hi(1024)|lo(1024)]

// ---------------------------------------------------------------------------
// PTX helpers (guarded)
// ---------------------------------------------------------------------------
#if HAS_TC
__device__ __forceinline__ uint32_t s2u(const void* p) {
    uint32_t a;
    asm("{ .reg .u64 t; cvta.to.shared.u64 t, %1; cvt.u32.u64 %0, t; }"
        : "=r"(a) : "l"(p));
    return a;
}
__device__ __forceinline__ uint32_t elect1() {
    uint32_t p;
    asm volatile("{\n\t.reg .pred p;\n\telect.sync _|p, 0xFFFFFFFF;\n\t"
                 "selp.b32 %0, 1, 0, p;\n\t}" : "=r"(p));
    return p;
}
#define SW128(x) ((x) ^ (((x) >> 3) & 0x70))

static constexpr uint64_t DESC_BASE =
    (2ull << 61) | (1ull << 46) | (64ull << 32) | (1ull << 16); // SW128, LBO=1, SBO=64
__device__ __forceinline__ uint64_t mkdesc(uint32_t a) {
    return DESC_BASE | ((uint64_t)(a >> 4) & 0x3FFF);
}

__device__ __forceinline__ void mma_ss_f16(uint32_t d, uint64_t a, uint64_t b,
                                           uint32_t id, uint32_t en) {
    asm volatile("{\n\t.reg .pred p;\n\tsetp.ne.u32 p, %5, 0;\n\t"
                 "tcgen05.mma.cta_group::1.kind::f16 [%0], %1, %2, %3, {%4,%4,%4,%4}, p;\n\t}"
                 :: "r"(d), "l"(a), "l"(b), "r"(id), "r"(0u), "r"(en) : "memory");
}

#define MBAR_INIT(a, c) \
    asm volatile("mbarrier.init.shared.b64 [%0], %1;" :: "r"(a), "r"(c) : "memory")
#define TC_COMMIT(a) \
    asm volatile("tcgen05.commit.cta_group::1.mbarrier::arrive::one.shared::cluster.b64 [%0];" \
                 :: "r"(a) : "memory")
#define WAIT_PARITY(mb, ph) do {                                              \
    asm volatile("{\n\t.reg .pred P1;\n\t"                                    \
        "WL_%=:\n\t"                                                          \
        "mbarrier.try_wait.parity.acquire.cta.shared::cta.b64 P1, [%0], %1, 0x989680;\n\t" \
        "@P1 bra.uni WD_%=;\n\t"                                              \
        "bra.uni WL_%=;\n\t"                                                  \
        "WD_%=:\n\t}" :: "r"(mb), "r"(ph) : "memory");                        \
} while (0)

#define LDTM_X32(r, a)                                                        \
    asm volatile("tcgen05.ld.sync.aligned.32x32b.x32.b32 "                    \
        "{%0, %1, %2, %3, %4, %5, %6, %7, "                                   \
        " %8, %9, %10, %11, %12, %13, %14, %15, "                             \
        " %16, %17, %18, %19, %20, %21, %22, %23, "                           \
        " %24, %25, %26, %27, %28, %29, %30, %31}, [%32];"                    \
        : "=r"((r)[0]),  "=r"((r)[1]),  "=r"((r)[2]),  "=r"((r)[3]),          \
          "=r"((r)[4]),  "=r"((r)[5]),  "=r"((r)[6]),  "=r"((r)[7]),          \
          "=r"((r)[8]),  "=r"((r)[9]),  "=r"((r)[10]), "=r"((r)[11]),         \
          "=r"((r)[12]), "=r"((r)[13]), "=r"((r)[14]), "=r"((r)[15]),         \
          "=r"((r)[16]), "=r"((r)[17]), "=r"((r)[18]), "=r"((r)[19]),         \
          "=r"((r)[20]), "=r"((r)[21]), "=r"((r)[22]), "=r"((r)[23]),         \
          "=r"((r)[24]), "=r"((r)[25]), "=r"((r)[26]), "=r"((r)[27]),         \
          "=r"((r)[28]), "=r"((r)[29]), "=r"((r)[30]), "=r"((r)[31])          \
        : "r"(a))
#endif // HAS_TC

// ---------------------------------------------------------------------------
// Kernel 1: assemble multi-scale filter, normalize. one block per head.
// ---------------------------------------------------------------------------
__global__ void build_filter_kernel(const float* __restrict__ k0,
                                    const float* __restrict__ k1,
                                    const float* __restrict__ k2,
                                    const float* __restrict__ k3) {
    int h   = blockIdx.x;
    int tid = threadIdx.x;             // 128 threads
    const float* ks0 = k0 + h * KDIM;
    const float* ks1 = k1 + h * KDIM;
    const float* ks2 = k2 + h * KDIM;
    const float* ks3 = k3 + h * KDIM;

    __shared__ float red[128];
    float vals[4];
    float ss = 0.0f;

    #pragma unroll
    for (int r = 0; r < 4; r++) {
        int t = tid + r * 128;
        float acc = 0.0f;
        #pragma unroll
        for (int i = 0; i < 4; i++) {
            int Li = KDIM << i;
            if (t < Li) {
                float coord = (t + 0.5f) / (float)(1 << i) - 0.5f;
                coord = fminf(fmaxf(coord, 0.0f), (float)(KDIM - 1));
                int   lo = (int)floorf(coord);
                int   hi = min(lo + 1, KDIM - 1);
                float w  = coord - (float)lo;
                const float* kp = (i == 0) ? ks0 : (i == 1) ? ks1 : (i == 2) ? ks2 : ks3;
                float v = kp[lo] * (1.0f - w) + kp[hi] * w;
                acc += v * (float)(1 << (3 - i));
            }
        }
        vals[r] = acc;
        ss += acc * acc;
    }

    red[tid] = ss;
    __syncthreads();
    for (int s = 64; s > 0; s >>= 1) {
        if (tid < s) red[tid] += red[tid + s];
        __syncthreads();
    }
    float inv = 1.0f / sqrtf(red[0]);

    #pragma unroll
    for (int r = 0; r < 4; r++) {
        int t = tid + r * 128;
        g_filt[h * KTOT + t] = vals[r] * inv;
    }
}

// ---------------------------------------------------------------------------
// Kernel 2: causal 512-tap FIR + D*u skip + exact gelu -> g_v
// ---------------------------------------------------------------------------
#define LT2  2048
#define TH2  256

__global__ __launch_bounds__(TH2) void fir_gelu_kernel(const float* __restrict__ u,
                                                       const float* __restrict__ D) {
    __shared__ float us[KTOT + LT2];
    __shared__ float ksm[KTOT];

    int l0  = blockIdx.x * LT2;
    int h   = blockIdx.y;
    int b   = blockIdx.z;
    int tid = threadIdx.x;

    const float* up = u + ((size_t)(b * HH + h)) * LL;

    for (int f = tid; f < (KTOT + LT2) / 4; f += TH2) {
        int gi = l0 - KTOT + f * 4;
        float4 v;
        if (gi >= 0) {
            v = *reinterpret_cast<const float4*>(up + gi);
        } else {
            v.x = 0.f; v.y = 0.f; v.z = 0.f; v.w = 0.f;
        }
        *reinterpret_cast<float4*>(&us[f * 4]) = v;
    }
    if (tid < KTOT / 4) {
        *reinterpret_cast<float4*>(&ksm[tid * 4]) =
            *reinterpret_cast<const float4*>(&g_filt[h * KTOT + tid * 4]);
    }
    __syncthreads();

    const int bw = KTOT + tid * 8;

    float acc[8];
    #pragma unroll
    for (int r = 0; r < 8; r++) acc[r] = 0.0f;

    float w[12];
    {
        float4 a = *reinterpret_cast<const float4*>(&us[bw - 4]);
        float4 c = *reinterpret_cast<const float4*>(&us[bw]);
        float4 e = *reinterpret_cast<const float4*>(&us[bw + 4]);
        w[0] = a.x; w[1] = a.y; w[2]  = a.z; w[3]  = a.w;
        w[4] = c.x; w[5] = c.y; w[6]  = c.z; w[7]  = c.w;
        w[8] = e.x; w[9] = e.y; w[10] = e.z; w[11] = e.w;
    }

    #pragma unroll 4
    for (int g = 0; g < KTOT / 4; g++) {
        if (g > 0) {
            #pragma unroll
            for (int idx = 11; idx >= 4; idx--) w[idx] = w[idx - 4];
            float4 nv = *reinterpret_cast<const float4*>(&us[bw - 4 * g - 4]);
            w[0] = nv.x; w[1] = nv.y; w[2] = nv.z; w[3] = nv.w;
        }
        float4 kv = *reinterpret_cast<const float4*>(&ksm[4 * g]);
        #pragma unroll
        for (int j = 0; j < 4; j++) {
            float kj = (j == 0) ? kv.x : (j == 1) ? kv.y : (j == 2) ? kv.z : kv.w;
            #pragma unroll
            for (int r = 0; r < 8; r++)
                acc[r] += kj * w[r - j + 4];
        }
    }

    float d = D[h];
    const float iS2 = 0.70710678118654752440f;
    float out8[8];
    #pragma unroll
    for (int r = 0; r < 8; r++) {
        float x = acc[r] + d * us[bw + r];
        out8[r] = 0.5f * x * (1.0f + erff(x * iS2));
    }

    float* vp = g_v + ((size_t)(b * HH + h)) * LL + l0 + tid * 8;
    *reinterpret_cast<float4*>(vp)     = make_float4(out8[0], out8[1], out8[2], out8[3]);
    *reinterpret_cast<float4*>(vp + 4) = make_float4(out8[4], out8[5], out8[6], out8[7]);
}

// ---------------------------------------------------------------------------
// Kernel 2b: transpose + bf16 hi/lo split: g_v[b][h][l] -> g_vt[b][l][hi|lo]
// ---------------------------------------------------------------------------
__global__ __launch_bounds__(256) void transpose_split_kernel() {
    __shared__ float ts[64][65];
    int l0 = blockIdx.x * 64;
    int h0 = blockIdx.y * 64;
    int b  = blockIdx.z;
    int t  = threadIdx.x;
    int tl = t & 63;
    int tr = t >> 6;                    // 0..3

    const float* vp = g_v + ((size_t)(b * HH + h0)) * LL + l0;
    #pragma unroll
    for (int i = 0; i < 16; i++) {
        int hh = tr + i * 4;
        ts[hh][tl] = vp[(size_t)hh * LL + tl];
    }
    __syncthreads();

    __nv_bfloat16* op = g_vt + ((size_t)b * LL + l0) * 2048;
    #pragma unroll
    for (int i = 0; i < 16; i++) {
        int ll = tr + i * 4;
        float x = ts[tl][ll];
        __nv_bfloat16 hi = __float2bfloat16(x);
        __nv_bfloat16 lo = __float2bfloat16(x - __bfloat162float(hi));
        op[(size_t)ll * 2048 + h0 + tl]        = hi;
        op[(size_t)ll * 2048 + 1024 + h0 + tl] = lo;
    }
}

// ---------------------------------------------------------------------------
// Kernel 2c: W -> bf16 hi/lo split
// ---------------------------------------------------------------------------
__global__ void wsplit_kernel(const float* __restrict__ W) {
    int o = blockIdx.x;
    for (int j = threadIdx.x; j < HH; j += blockDim.x) {
        float x = W[(size_t)o * HH + j];
        __nv_bfloat16 hi = __float2bfloat16(x);
        __nv_bfloat16 lo = __float2bfloat16(x - __bfloat162float(hi));
        g_ws[(size_t)o * 2048 + j]        = hi;
        g_ws[(size_t)o * 2048 + 1024 + j] = lo;
    }
}

// ---------------------------------------------------------------------------
// Kernel 3: GEMM. tcgen05 split-bf16 on sm_103a cubins; SIMT fp32 fallback
// on baseline-family cubins (same symbol, same launch config, both correct).
// D[l=128, o=256] per CTA. K' = 3072 = 3 x 1024: (hi,hi), (lo,hi), (hi,lo)
// ---------------------------------------------------------------------------
#define GM     128
#define GN     256
#define GK     64
#define NCHUNK 48

#define SA0   0
#define SA1   (16 * 1024)
#define SB0   (32 * 1024)
#define SB1   (64 * 1024)
#define SMB   (96 * 1024)           // 2 mbarriers
#define STM   (96 * 1024 + 32)      // tmem ptr
#define SBIAS (96 * 1024 + 64)      // 256 floats
#define SMEM_TOTAL_G (96 * 1024 + 64 + 1024)

#if HAS_TC
static constexpr uint32_t IDESC =
    (1u << 4) | (1u << 7) | (1u << 10) | ((GN / 8) << 17) | ((GM / 16) << 24);
#endif

__global__ void __launch_bounds__(256, 1)
gemm_kernel(const float* __restrict__ bias, float* __restrict__ out,
            const float* __restrict__ W) {
    extern __shared__ char smem[];
    int tid  = threadIdx.x;
    int l0 = blockIdx.x * GM;
    int o0 = blockIdx.y * GN;
    int b  = blockIdx.z;

#if HAS_TC
    uint32_t sb = s2u(smem);
    int wid  = tid >> 5;
    int lane = tid & 31;

    if (wid == 0) {
        asm volatile("tcgen05.alloc.cta_group::1.sync.aligned.shared::cta.b32 [%0], %1;"
                     :: "r"(sb + STM), "r"(256) : "memory");
    }
    if (tid == 0) { MBAR_INIT(sb + SMB, 1); MBAR_INIT(sb + SMB + 8, 1); }
    ((float*)(smem + SBIAS))[tid] = bias[o0 + tid];
    __syncthreads();
    uint32_t tmem;
    asm volatile("ld.shared.b32 %0, [%1];" : "=r"(tmem) : "r"(sb + STM));

    const __nv_bfloat16* vt = g_vt + (size_t)b * LL * 2048;

    uint4 ra[4], rb[8];

#define LDG_CHUNK(c)                                                          \
    do {                                                                      \
        int seg  = (c) >> 4;                                                  \
        int kc   = ((c) & 15) * GK;                                           \
        int aoff = (seg == 1) ? 1024 : 0;                                     \
        int boff = (seg == 2) ? 1024 : 0;                                     \
        const __nv_bfloat16* ap = vt + (size_t)l0 * 2048 + aoff + kc;         \
        const __nv_bfloat16* bp = g_ws + (size_t)o0 * 2048 + boff + kc;       \
        _Pragma("unroll")                                                     \
        for (int i = 0; i < 4; i++) {                                         \
            int idx = tid + i * 256; int r = idx >> 3, q = idx & 7;           \
            ra[i] = *reinterpret_cast<const uint4*>(ap + (size_t)r * 2048 + q * 8); \
        }                                                                     \
        _Pragma("unroll")                                                     \
        for (int i = 0; i < 8; i++) {                                         \
            int idx = tid + i * 256; int r = idx >> 3, q = idx & 7;           \
            rb[i] = *reinterpret_cast<const uint4*>(bp + (size_t)r * 2048 + q * 8); \
        }                                                                     \
    } while (0)

#define STS_CHUNK(p)                                                          \
    do {                                                                      \
        char* As = smem + ((p) ? SA1 : SA0);                                  \
        char* Bs = smem + ((p) ? SB1 : SB0);                                  \
        _Pragma("unroll")                                                     \
        for (int i = 0; i < 4; i++) {                                         \
            int idx = tid + i * 256; int r = idx >> 3, q = idx & 7;           \
            *reinterpret_cast<uint4*>(As + SW128(r * 128 + q * 16)) = ra[i];  \
        }                                                                     \
        _Pragma("unroll")                                                     \
        for (int i = 0; i < 8; i++) {                                         \
            int idx = tid + i * 256; int r = idx >> 3, q = idx & 7;           \
            *reinterpret_cast<uint4*>(Bs + SW128(r * 128 + q * 16)) = rb[i];  \
        }                                                                     \
    } while (0)

    LDG_CHUNK(0);
    STS_CHUNK(0);
    asm volatile("fence.proxy.async.shared::cta;" ::: "memory");
    __syncthreads();

    uint32_t ph0 = 0, ph1 = 0;
    for (int c = 0; c < NCHUNK; c++) {
        int p = c & 1;
        if (wid == 0) {
            if (elect1()) {
                uint64_t ad = mkdesc(sb + (p ? SA1 : SA0));
                uint64_t bd = mkdesc(sb + (p ? SB1 : SB0));
                #pragma unroll
                for (int k = 0; k < 4; k++)
                    mma_ss_f16(tmem, ad + k * 2, bd + k * 2, IDESC,
                               (c > 0 || k > 0) ? 1u : 0u);
                TC_COMMIT(sb + SMB + p * 8);
            }
        }
        if (c + 1 < NCHUNK) LDG_CHUNK(c + 1);
        if (c >= 1) {
            uint32_t q  = p ^ 1;
            uint32_t mb = sb + SMB + q * 8;
            uint32_t ph = q ? ph1 : ph0;
            WAIT_PARITY(mb, ph);
            if (q) ph1 ^= 1; else ph0 ^= 1;
        }
        __syncthreads();
        if (c + 1 < NCHUNK) {
            STS_CHUNK(p ^ 1);
            asm volatile("fence.proxy.async.shared::cta;" ::: "memory");
        }
        __syncthreads();
    }
    WAIT_PARITY(sb + SMB + 8, ph1);
    asm volatile("tcgen05.fence::after_thread_sync;" ::: "memory");

    // epilogue: lane = l (coalesced along l), col = o, add bias
    int sub  = wid & 3;
    int half = wid >> 2;
    int lg   = l0 + sub * 32 + lane;
    const float* bs = (const float*)(smem + SBIAS);
    #pragma unroll
    for (int it = 0; it < 4; it++) {
        int cb = half * 128 + it * 32;
        uint32_t r[32];
        LDTM_X32(r, tmem + cb);
        asm volatile("tcgen05.wait::ld.sync.aligned;" ::: "memory");
        float* op = out + ((size_t)(b * HH + o0 + cb)) * LL + lg;
        #pragma unroll
        for (int j = 0; j < 32; j++)
            op[(size_t)j * LL] = __uint_as_float(r[j]) + bs[cb + j];
    }
    __syncthreads();
    if (wid == 0) {
        asm volatile("tcgen05.relinquish_alloc_permit.cta_group::1.sync.aligned;");
        asm volatile("tcgen05.dealloc.cta_group::1.sync.aligned.b32 %0, %1;"
                     :: "r"(tmem), "r"(256));
    }
#undef LDG_CHUNK
#undef STS_CHUNK

#else  // ---------------- SIMT fp32 fallback (baseline-family cubin) -------
    // tile: 128 l (blockIdx.x) x 256 o (blockIdx.y); 256 threads,
    // thread micro-tile 16 o x 8 l. K from g_v / W directly.
    float (*Ws)[GN] = (float (*)[GN])(smem);               // [16][256] 16KB
    float (*Vs)[GM] = (float (*)[GM])(smem + 16 * GN * 4); // [16][128]  8KB

    int tx = tid & 15;                 // l group
    int ty = tid >> 4;                 // o group

    float acc[16][8];
    #pragma unroll
    for (int i = 0; i < 16; i++)
        #pragma unroll
        for (int j = 0; j < 8; j++) acc[i][j] = 0.0f;

    const float* vbase = g_v + ((size_t)b * HH) * LL + l0;

    for (int kb = 0; kb < HH; kb += 16) {
        #pragma unroll
        for (int i = 0; i < 16; i++) {
            int idx = tid + i * 256;
            int kk  = idx & 15;
            int mm  = idx >> 4;
            Ws[kk][mm] = W[(size_t)(o0 + mm) * HH + kb + kk];
        }
        #pragma unroll
        for (int i = 0; i < 8; i++) {
            int idx = tid + i * 256;
            int ll  = idx & 127;
            int kk  = idx >> 7;
            Vs[kk][ll] = vbase[(size_t)(kb + kk) * LL + ll];
        }
        __syncthreads();

        #pragma unroll
        for (int kk = 0; kk < 16; kk++) {
            float bf[8];
            #pragma unroll
            for (int j = 0; j < 8; j++) bf[j] = Vs[kk][tx * 8 + j];
            #pragma unroll
            for (int i = 0; i < 16; i++) {
                float a = Ws[kk][ty * 16 + i];
                #pragma unroll
                for (int j = 0; j < 8; j++)
                    acc[i][j] += a * bf[j];
            }
        }
        __syncthreads();
    }

    #pragma unroll
    for (int i = 0; i < 16; i++) {
        int o = o0 + ty * 16 + i;
        float bb = bias[o];
        float* op = out + ((size_t)(b * HH + o)) * LL + l0 + tx * 8;
        #pragma unroll
        for (int j = 0; j < 8; j++)
            op[j] = acc[i][j] + bb;
    }
#endif
}

// ---------------------------------------------------------------------------
extern "C" void kernel_launch(void* const* d_in, const int* in_sizes, int n_in,
                              void* d_out, int out_size) {
    const float* u  = (const float*)d_in[0];
    const float* k0 = (const float*)d_in[1];
    const float* k1 = (const float*)d_in[2];
    const float* k2 = (const float*)d_in[3];
    const float* k3 = (const float*)d_in[4];
    const float* D  = (const float*)d_in[5];
    const float* W  = (const float*)d_in[6];
    const float* b  = (const float*)d_in[7];
    float* out = (float*)d_out;

    build_filter_kernel<<<HH, 128>>>(k0, k1, k2, k3);

    dim3 g2(LL / LT2, HH, BB);
    fir_gelu_kernel<<<g2, TH2>>>(u, D);

    dim3 gt(LL / 64, HH / 64, BB);
    transpose_split_kernel<<<gt, 256>>>();

    wsplit_kernel<<<HH, 256>>>(W);

    cudaFuncSetAttribute(gemm_kernel, cudaFuncAttributeMaxDynamicSharedMemorySize,
                         SMEM_TOTAL_G);
    dim3 g3(LL / GM, HH / GN, BB);
    gemm_kernel<<<g3, 256, SMEM_TOTAL_G>>>(b, out, W);
}